// round 1
// baseline (speedup 1.0000x reference)
#include <cuda_runtime.h>
#include <math.h>

#define NN 100000
#define EE 600000
#define DD 128
#define SS 3
#define LL 2
#define GG 64
#define OUTD 2

// ---------------- device scratch (no allocations allowed) ----------------
__device__ float g_x[NN * DD];        // current pass input
__device__ float g_h[NN * DD];        // GGC hidden state
__device__ float g_m[NN * DD];        // h @ W
__device__ float g_agg[NN * DD];      // scattered messages
__device__ float g_acc[NN * DD];      // sum over edge sets
__device__ float g_gi[NN * 3 * DD];   // agg @ wih^T + bih
__device__ float g_gh[NN * 3 * DD];   // h   @ whh^T + bhh
__device__ float g_deg[SS * NN];      // in-degree per type -> inverse
__device__ float g_wt[SS * LL * DD * DD]; // W transposed to [j,k]
__device__ float g_pool[GG * DD];
__device__ float g_cnt[GG];

// ---------------- small utility kernels ----------------
__global__ void zero_kernel(float* __restrict__ p, int n4) {
    int i = blockIdx.x * blockDim.x + threadIdx.x;
    if (i < n4) ((float4*)p)[i] = make_float4(0.f, 0.f, 0.f, 0.f);
}

__global__ void copy_kernel(float* __restrict__ dst, const float* __restrict__ src, int n4) {
    int i = blockIdx.x * blockDim.x + threadIdx.x;
    if (i < n4) ((float4*)dst)[i] = ((const float4*)src)[i];
}

__global__ void scale_copy_kernel(float* __restrict__ dst, const float* __restrict__ src,
                                  float s, int n4) {
    int i = blockIdx.x * blockDim.x + threadIdx.x;
    if (i < n4) {
        float4 v = ((const float4*)src)[i];
        v.x *= s; v.y *= s; v.z *= s; v.w *= s;
        ((float4*)dst)[i] = v;
    }
}

__global__ void add_kernel(float* __restrict__ dst, const float* __restrict__ src, int n4) {
    int i = blockIdx.x * blockDim.x + threadIdx.x;
    if (i < n4) {
        float4 a = ((float4*)dst)[i];
        float4 b = ((const float4*)src)[i];
        a.x += b.x; a.y += b.y; a.z += b.z; a.w += b.w;
        ((float4*)dst)[i] = a;
    }
}

__global__ void transpose_w_kernel(const float* __restrict__ W, float* __restrict__ Wt) {
    int idx = blockIdx.x * blockDim.x + threadIdx.x;
    int total = SS * LL * DD * DD;
    if (idx >= total) return;
    int mat = idx / (DD * DD);
    int rem = idx - mat * DD * DD;
    int k = rem / DD;
    int j = rem - k * DD;
    Wt[mat * DD * DD + j * DD + k] = W[idx];
}

__global__ void deg_count_kernel(const int* __restrict__ dst, const int* __restrict__ attr,
                                 float* __restrict__ deg, int E) {
    int e = blockIdx.x * blockDim.x + threadIdx.x;
    if (e >= E) return;
    atomicAdd(&deg[attr[e] * NN + dst[e]], 1.0f);
}

__global__ void invdeg_kernel(float* __restrict__ deg, int n) {
    int i = blockIdx.x * blockDim.x + threadIdx.x;
    if (i < n) deg[i] = 1.0f / fmaxf(deg[i], 1.0f);
}

// ---------------- edge scatter: agg[dst] += m[src] for edges of type s ------
__global__ void edge_scatter_kernel(const int* __restrict__ src, const int* __restrict__ dst,
                                    const int* __restrict__ attr, int s,
                                    const float* __restrict__ m, float* __restrict__ agg,
                                    int E) {
    int gtid = blockIdx.x * blockDim.x + threadIdx.x;
    int e = gtid >> 5;
    int lane = gtid & 31;
    if (e >= E) return;
    if (attr[e] != s) return;
    int sn = src[e];
    int dn = dst[e];
    float4 v = *(const float4*)(m + (size_t)sn * DD + lane * 4);
    float* o = agg + (size_t)dn * DD + lane * 4;
    atomicAdd(o + 0, v.x);
    atomicAdd(o + 1, v.y);
    atomicAdd(o + 2, v.z);
    atomicAdd(o + 3, v.w);
}

// ---------------- SGEMM NT: C[M,J] = (rowscale .* A[M,128]) @ B[J,128]^T + bias -----
// K fixed at 128. 128x128 tile, 8x8 microtiles, 256 threads, global prefetch.
__global__ void __launch_bounds__(256)
sgemm_nt_kernel(const float* __restrict__ A, const float* __restrict__ B,
                float* __restrict__ C, const float* __restrict__ bias,
                const float* __restrict__ rowscale, int M, int J) {
    __shared__ __align__(16) float As[8][128];
    __shared__ __align__(16) float Bs[8][128];

    int tid = threadIdx.x;
    int bm = blockIdx.x * 128;
    int bn = blockIdx.y * 128;

    int lrow = tid >> 1;            // 0..127
    int lcol = (tid & 1) * 4;       // 0 or 4
    int mrow = bm + lrow;
    bool mvalid = (mrow < M);

    float rs = 1.0f;
    if (rowscale != nullptr && mvalid) rs = rowscale[mrow];

    const float* Aptr = A + (size_t)mrow * 128 + lcol;
    const float* Bptr = B + (size_t)(bn + lrow) * 128 + lcol;

    int mb = (tid >> 4) << 3;       // row base of microtile
    int nb = (tid & 15) << 3;       // col base of microtile

    float acc[8][8];
#pragma unroll
    for (int i = 0; i < 8; i++)
#pragma unroll
        for (int j = 0; j < 8; j++) acc[i][j] = 0.f;

    float4 av = mvalid ? *(const float4*)(Aptr) : make_float4(0.f, 0.f, 0.f, 0.f);
    float4 bv = *(const float4*)(Bptr);

#pragma unroll
    for (int kc = 0; kc < 128; kc += 8) {
        __syncthreads();
        As[lcol + 0][lrow] = av.x * rs;
        As[lcol + 1][lrow] = av.y * rs;
        As[lcol + 2][lrow] = av.z * rs;
        As[lcol + 3][lrow] = av.w * rs;
        Bs[lcol + 0][lrow] = bv.x;
        Bs[lcol + 1][lrow] = bv.y;
        Bs[lcol + 2][lrow] = bv.z;
        Bs[lcol + 3][lrow] = bv.w;
        __syncthreads();

        if (kc < 120) {
            av = mvalid ? *(const float4*)(Aptr + kc + 8) : make_float4(0.f, 0.f, 0.f, 0.f);
            bv = *(const float4*)(Bptr + kc + 8);
        }

#pragma unroll
        for (int kk = 0; kk < 8; kk++) {
            float a[8], b[8];
            *(float4*)(a)     = *(const float4*)&As[kk][mb];
            *(float4*)(a + 4) = *(const float4*)&As[kk][mb + 4];
            *(float4*)(b)     = *(const float4*)&Bs[kk][nb];
            *(float4*)(b + 4) = *(const float4*)&Bs[kk][nb + 4];
#pragma unroll
            for (int i = 0; i < 8; i++)
#pragma unroll
                for (int j = 0; j < 8; j++) acc[i][j] = fmaf(a[i], b[j], acc[i][j]);
        }
    }

    float bb[8];
#pragma unroll
    for (int j = 0; j < 8; j++) bb[j] = (bias != nullptr) ? bias[bn + nb + j] : 0.f;

#pragma unroll
    for (int i = 0; i < 8; i++) {
        int row = bm + mb + i;
        if (row >= M) continue;
        float* crow = C + (size_t)row * J + bn + nb;
#pragma unroll
        for (int j = 0; j < 8; j += 4) {
            float4 v;
            v.x = acc[i][j + 0] + bb[j + 0];
            v.y = acc[i][j + 1] + bb[j + 1];
            v.z = acc[i][j + 2] + bb[j + 2];
            v.w = acc[i][j + 3] + bb[j + 3];
            *(float4*)(crow + j) = v;
        }
    }
}

// ---------------- GRU elementwise combine ----------------
__device__ __forceinline__ float sigf(float x) { return 1.0f / (1.0f + expf(-x)); }

__global__ void gru_combine_kernel(const float* __restrict__ gi, const float* __restrict__ gh,
                                   const float* __restrict__ hold, float* __restrict__ hout) {
    int idx = blockIdx.x * blockDim.x + threadIdx.x;   // over NN*32 float4 slots
    if (idx >= NN * 32) return;
    int n = idx >> 5;
    int c = (idx & 31) * 4;
    const float* gir = gi + (size_t)n * 384;
    const float* ghr = gh + (size_t)n * 384;
    float4 ir = *(const float4*)(gir + c);
    float4 iz = *(const float4*)(gir + 128 + c);
    float4 in4 = *(const float4*)(gir + 256 + c);
    float4 hr = *(const float4*)(ghr + c);
    float4 hz = *(const float4*)(ghr + 128 + c);
    float4 hn = *(const float4*)(ghr + 256 + c);
    float4 h = *(const float4*)(hold + (size_t)n * 128 + c);

    float4 o;
    {
        float r = sigf(ir.x + hr.x), z = sigf(iz.x + hz.x);
        float nn = tanhf(in4.x + r * hn.x);
        o.x = (1.f - z) * nn + z * h.x;
    }
    {
        float r = sigf(ir.y + hr.y), z = sigf(iz.y + hz.y);
        float nn = tanhf(in4.y + r * hn.y);
        o.y = (1.f - z) * nn + z * h.y;
    }
    {
        float r = sigf(ir.z + hr.z), z = sigf(iz.z + hz.z);
        float nn = tanhf(in4.z + r * hn.z);
        o.z = (1.f - z) * nn + z * h.z;
    }
    {
        float r = sigf(ir.w + hr.w), z = sigf(iz.w + hz.w);
        float nn = tanhf(in4.w + r * hn.w);
        o.w = (1.f - z) * nn + z * h.w;
    }
    *(float4*)(hout + (size_t)n * 128 + c) = o;
}

// ---------------- pooling ----------------
__global__ void cnt_kernel(const int* __restrict__ batch, float* __restrict__ cnt, int n) {
    int i = blockIdx.x * blockDim.x + threadIdx.x;
    if (i < n) atomicAdd(&cnt[batch[i]], 1.0f);
}

__global__ void pool_kernel(const float* __restrict__ x, const int* __restrict__ batch,
                            float* __restrict__ pool) {
    int idx = blockIdx.x * blockDim.x + threadIdx.x;   // over NN*32
    if (idx >= NN * 32) return;
    int n = idx >> 5;
    int c = (idx & 31) * 4;
    int g = batch[n];
    float4 v = *(const float4*)(x + (size_t)n * 128 + c);
    float* o = pool + (size_t)g * 128 + c;
    atomicAdd(o + 0, v.x);
    atomicAdd(o + 1, v.y);
    atomicAdd(o + 2, v.z);
    atomicAdd(o + 3, v.w);
}

// ---------------- final MLP (single block) ----------------
__global__ void mlp_kernel(const float* __restrict__ pool, const float* __restrict__ cnt,
                           const float* __restrict__ pt,
                           const float* __restrict__ fc1w, const float* __restrict__ fc1b,
                           const float* __restrict__ fc2w, const float* __restrict__ fc2b,
                           const float* __restrict__ fclw, const float* __restrict__ fclb,
                           float* __restrict__ out) {
    __shared__ float h1[GG * 80];
    __shared__ float h2[GG * 80];
    int tid = threadIdx.x;

    for (int t = tid; t < GG * 80; t += blockDim.x) {
        int g = t / 80, j = t - (t / 80) * 80;
        float ic = 1.0f / fmaxf(cnt[g], 1.0f);
        float acc = fc1b[j];
        const float* w = fc1w + j * 129;
        const float* p = pool + g * 128;
        for (int k = 0; k < 128; k++) acc = fmaf(p[k] * ic, w[k], acc);
        acc = fmaf(pt[g], w[128], acc);
        h1[t] = acc > 0.f ? acc : 0.01f * acc;
    }
    __syncthreads();
    for (int t = tid; t < GG * 80; t += blockDim.x) {
        int g = t / 80, j = t - (t / 80) * 80;
        float acc = fc2b[j];
        const float* w = fc2w + j * 80;
        const float* hh = h1 + g * 80;
        for (int k = 0; k < 80; k++) acc = fmaf(hh[k], w[k], acc);
        h2[t] = acc > 0.f ? acc : 0.01f * acc;
    }
    __syncthreads();
    for (int t = tid; t < GG * OUTD; t += blockDim.x) {
        int g = t / OUTD, o = t - (t / OUTD) * OUTD;
        float acc = fclb[o];
        const float* w = fclw + o * 80;
        const float* hh = h2 + g * 80;
        for (int k = 0; k < 80; k++) acc = fmaf(hh[k], w[k], acc);
        out[t] = acc;
    }
}

// ---------------- host launcher ----------------
extern "C" void kernel_launch(void* const* d_in, const int* in_sizes, int n_in,
                              void* d_out, int out_size) {
    (void)in_sizes; (void)n_in; (void)out_size;
    const float* x     = (const float*)d_in[0];
    const int*   eidx  = (const int*)d_in[1];
    const int*   eattr = (const int*)d_in[2];
    const int*   batch = (const int*)d_in[3];
    const float* pt    = (const float*)d_in[4];
    const float* W     = (const float*)d_in[5];
    const float* wih   = (const float*)d_in[6];
    const float* whh   = (const float*)d_in[7];
    const float* bih   = (const float*)d_in[8];
    const float* bhh   = (const float*)d_in[9];
    const float* fc1w  = (const float*)d_in[10];
    const float* fc1b  = (const float*)d_in[11];
    const float* fc2w  = (const float*)d_in[12];
    const float* fc2b  = (const float*)d_in[13];
    const float* fclw  = (const float*)d_in[14];
    const float* fclb  = (const float*)d_in[15];
    float* out = (float*)d_out;

    const int* src = eidx;
    const int* dst = eidx + EE;

    float *xp, *hp, *mp, *aggp, *accp, *gip, *ghp, *degp, *wtp, *poolp, *cntp;
    cudaGetSymbolAddress((void**)&xp,   g_x);
    cudaGetSymbolAddress((void**)&hp,   g_h);
    cudaGetSymbolAddress((void**)&mp,   g_m);
    cudaGetSymbolAddress((void**)&aggp, g_agg);
    cudaGetSymbolAddress((void**)&accp, g_acc);
    cudaGetSymbolAddress((void**)&gip,  g_gi);
    cudaGetSymbolAddress((void**)&ghp,  g_gh);
    cudaGetSymbolAddress((void**)&degp, g_deg);
    cudaGetSymbolAddress((void**)&wtp,  g_wt);
    cudaGetSymbolAddress((void**)&poolp, g_pool);
    cudaGetSymbolAddress((void**)&cntp, g_cnt);

    const int ND4 = NN * DD / 4;
    const int TB = 256;
    dim3 gemm_grid1((NN + 127) / 128, 1);
    dim3 gemm_grid3((NN + 127) / 128, 3);

    // --- preprocessing ---
    zero_kernel<<<(SS * NN / 4 + TB - 1) / TB, TB>>>(degp, SS * NN / 4);
    deg_count_kernel<<<(EE + TB - 1) / TB, TB>>>(dst, eattr, degp, EE);
    invdeg_kernel<<<(SS * NN + TB - 1) / TB, TB>>>(degp, SS * NN);
    transpose_w_kernel<<<(SS * LL * DD * DD + TB - 1) / TB, TB>>>(W, wtp);
    copy_kernel<<<(ND4 + TB - 1) / TB, TB>>>(xp, x, ND4);

    for (int pass = 0; pass < 2; pass++) {
        zero_kernel<<<(ND4 + TB - 1) / TB, TB>>>(accp, ND4);
        for (int s = 0; s < SS; s++) {
            for (int i = 0; i < LL; i++) {
                const float* hin = (i == 0) ? xp : hp;
                // m = hin @ W[s,i]
                sgemm_nt_kernel<<<gemm_grid1, TB>>>(hin, wtp + (size_t)(s * LL + i) * DD * DD,
                                                    mp, nullptr, nullptr, NN, DD);
                // agg = scatter-sum of m over type-s edges
                zero_kernel<<<(ND4 + TB - 1) / TB, TB>>>(aggp, ND4);
                edge_scatter_kernel<<<((size_t)EE * 32 + TB - 1) / TB, TB>>>(
                    src, dst, eattr, s, mp, aggp, EE);
                // gi = (agg * invdeg) @ wih^T + bih ; gh = hin @ whh^T + bhh
                sgemm_nt_kernel<<<gemm_grid3, TB>>>(aggp, wih + (size_t)s * 3 * DD * DD,
                                                    gip, bih + s * 3 * DD, degp + s * NN,
                                                    NN, 3 * DD);
                sgemm_nt_kernel<<<gemm_grid3, TB>>>(hin, whh + (size_t)s * 3 * DD * DD,
                                                    ghp, bhh + s * 3 * DD, nullptr,
                                                    NN, 3 * DD);
                gru_combine_kernel<<<(NN * 32 + TB - 1) / TB, TB>>>(gip, ghp, hin, hp);
            }
            add_kernel<<<(ND4 + TB - 1) / TB, TB>>>(accp, hp, ND4);
        }
        scale_copy_kernel<<<(ND4 + TB - 1) / TB, TB>>>(xp, accp, 1.0f / 3.0f, ND4);
    }

    // --- pooling + MLP ---
    zero_kernel<<<(GG * DD / 4 + TB - 1) / TB, TB>>>(poolp, GG * DD / 4);
    zero_kernel<<<1, TB>>>(cntp, GG / 4);
    cnt_kernel<<<(NN + TB - 1) / TB, TB>>>(batch, cntp, NN);
    pool_kernel<<<(NN * 32 + TB - 1) / TB, TB>>>(xp, batch, poolp);
    mlp_kernel<<<1, 256>>>(poolp, cntp, pt, fc1w, fc1b, fc2w, fc2b, fclw, fclb, out);
}

// round 3
// speedup vs baseline: 1.2849x; 1.2849x over previous
#include <cuda_runtime.h>
#include <math.h>
#include <stdint.h>
#include <mma.h>

using namespace nvcuda;

#define NN 100000
#define NP 100096            // padded to multiple of 128
#define EE 600000
#define DD 128
#define SS 3
#define GG 64
#define OUTD 2

// ---------------- device scratch (padded node buffers) ----------------
__device__ float g_x[NP * DD];
__device__ float g_h[NP * DD];
__device__ float g_agg[NP * DD];
__device__ float g_acc[NN * DD];
__device__ float g_gi[NP * 3 * DD];
__device__ float g_gh[NP * 3 * DD];
__device__ float g_deg[SS * NP];
__device__ float g_wc[SS * 2 * 3 * DD * DD];   // 6 x [384,128]
__device__ float g_pool[GG * DD];
__device__ float g_cnt[GG];
__device__ int   g_bsrc[EE];
__device__ int   g_bdst[EE];
__device__ int   g_bmeta[10];                  // cnt[0:3], cur[3:6], off[6:10]

// ---------------- tiny utils ----------------
__global__ void zero_kernel(float* __restrict__ p, int n4) {
    int i = blockIdx.x * blockDim.x + threadIdx.x;
    if (i < n4) ((float4*)p)[i] = make_float4(0.f, 0.f, 0.f, 0.f);
}
__global__ void zero_ints(int* __restrict__ p, int n) {
    int i = blockIdx.x * blockDim.x + threadIdx.x;
    if (i < n) p[i] = 0;
}
__global__ void copy_kernel(float* __restrict__ dst, const float* __restrict__ src, int n4) {
    int i = blockIdx.x * blockDim.x + threadIdx.x;
    if (i < n4) ((float4*)dst)[i] = ((const float4*)src)[i];
}
__global__ void scale_copy_kernel(float* __restrict__ dst, const float* __restrict__ src,
                                  float s, int n4) {
    int i = blockIdx.x * blockDim.x + threadIdx.x;
    if (i < n4) {
        float4 v = ((const float4*)src)[i];
        v.x *= s; v.y *= s; v.z *= s; v.w *= s;
        ((float4*)dst)[i] = v;
    }
}
__global__ void add_kernel(float* __restrict__ dst, const float* __restrict__ src, int n4) {
    int i = blockIdx.x * blockDim.x + threadIdx.x;
    if (i < n4) {
        float4 a = ((float4*)dst)[i];
        float4 b = ((const float4*)src)[i];
        a.x += b.x; a.y += b.y; a.z += b.z; a.w += b.w;
        ((float4*)dst)[i] = a;
    }
}

// ---------------- degree / bucketing ----------------
__global__ void deg_count_kernel(const int* __restrict__ dst, const int* __restrict__ attr,
                                 float* __restrict__ deg, int E) {
    int e = blockIdx.x * blockDim.x + threadIdx.x;
    if (e >= E) return;
    atomicAdd(&deg[attr[e] * NP + dst[e]], 1.0f);
}
__global__ void invdeg_kernel(float* __restrict__ deg, int n) {
    int i = blockIdx.x * blockDim.x + threadIdx.x;
    if (i < n) deg[i] = 1.0f / fmaxf(deg[i], 1.0f);
}
__global__ void bucket_count_kernel(const int* __restrict__ attr, int* __restrict__ meta, int E) {
    int e = blockIdx.x * blockDim.x + threadIdx.x;
    if (e < E) atomicAdd(&meta[attr[e]], 1);
}
__global__ void bucket_scan_kernel(int* __restrict__ meta) {
    meta[6] = 0;
    meta[7] = meta[0];
    meta[8] = meta[0] + meta[1];
    meta[9] = meta[0] + meta[1] + meta[2];
}
__global__ void bucket_fill_kernel(const int* __restrict__ src, const int* __restrict__ dst,
                                   const int* __restrict__ attr, int* __restrict__ meta,
                                   int* __restrict__ bsrc, int* __restrict__ bdst, int E) {
    int e = blockIdx.x * blockDim.x + threadIdx.x;
    if (e >= E) return;
    int s = attr[e];
    int p = meta[6 + s] + atomicAdd(&meta[3 + s], 1);
    bsrc[p] = src[e];
    bdst[p] = dst[e];
}

// ---------------- scatter: agg[dst] += feat[src] over bucketed type-s edges ----
__global__ void edge_scatter_bucket(const int* __restrict__ bsrc, const int* __restrict__ bdst,
                                    const int* __restrict__ meta, int s,
                                    const float* __restrict__ feat, float* __restrict__ agg) {
    int lane = threadIdx.x & 31;
    int warp = (blockIdx.x * blockDim.x + threadIdx.x) >> 5;
    int nw = (gridDim.x * blockDim.x) >> 5;
    int b = meta[6 + s], e = meta[7 + s];
    for (int i = b + warp; i < e; i += nw) {
        int sn = bsrc[i];
        int dn = bdst[i];
        float4 v = *(const float4*)(feat + (size_t)sn * DD + lane * 4);
        float* o = agg + (size_t)dn * DD + lane * 4;
        asm volatile("red.global.add.v4.f32 [%0], {%1,%2,%3,%4};"
                     :: "l"(o), "f"(v.x), "f"(v.y), "f"(v.z), "f"(v.w) : "memory");
    }
}

// ================= WMMA tf32 GEMM: C[M,J] = (rowscale.*A[M,128]) @ B[J,128]^T + bias ====
// M must be a multiple of 128 (buffers padded). CTA tile 128x64, K=128 resident.
#define TM 128
#define TN 64
#define LDT 136
#define GEMM_SMEM ((TM + TN) * LDT * 4)   // 104448 bytes

__device__ __forceinline__ float tf32r(float x) {
    float y;
    asm("cvt.rna.tf32.f32 %0, %1;" : "=f"(y) : "f"(x));
    return y;
}

__global__ void __launch_bounds__(256)
wmma_gemm_nt(const float* __restrict__ A, const float* __restrict__ B,
             float* __restrict__ C, const float* __restrict__ bias,
             const float* __restrict__ rowscale, int J) {
    extern __shared__ float sm[];
    float* As = sm;                 // [TM][LDT]
    float* Bs = sm + TM * LDT;      // [TN][LDT]
    int tid = threadIdx.x;
    int bm = blockIdx.y * TM;
    int bn = blockIdx.x * TN;

    // load A tile (TM x 128), tf32-rounded, optional row scale
    for (int slot = tid; slot < TM * 32; slot += 256) {
        int r = slot >> 5;
        int c4 = (slot & 31) * 4;
        float4 v = *(const float4*)(A + (size_t)(bm + r) * 128 + c4);
        if (rowscale != nullptr) {
            float rs = rowscale[bm + r];
            v.x *= rs; v.y *= rs; v.z *= rs; v.w *= rs;
        }
        v.x = tf32r(v.x); v.y = tf32r(v.y); v.z = tf32r(v.z); v.w = tf32r(v.w);
        *(float4*)(As + r * LDT + c4) = v;
    }
    // load B tile (TN x 128)
    for (int slot = tid; slot < TN * 32; slot += 256) {
        int r = slot >> 5;
        int c4 = (slot & 31) * 4;
        float4 v = *(const float4*)(B + (size_t)(bn + r) * 128 + c4);
        v.x = tf32r(v.x); v.y = tf32r(v.y); v.z = tf32r(v.z); v.w = tf32r(v.w);
        *(float4*)(Bs + r * LDT + c4) = v;
    }
    __syncthreads();

    int warp = tid >> 5;
    int wm = warp >> 1;          // 0..3 -> 32-row band
    int wn = warp & 1;           // 0..1 -> 32-col band
    int row0 = wm * 32;
    int col0 = wn * 32;

    wmma::fragment<wmma::accumulator, 16, 16, 8, float> acc[2][2];
#pragma unroll
    for (int i = 0; i < 2; i++)
#pragma unroll
        for (int j = 0; j < 2; j++) wmma::fill_fragment(acc[i][j], 0.0f);

#pragma unroll
    for (int k = 0; k < 16; k++) {
        wmma::fragment<wmma::matrix_a, 16, 16, 8, wmma::precision::tf32, wmma::row_major> a[2];
        wmma::fragment<wmma::matrix_b, 16, 16, 8, wmma::precision::tf32, wmma::col_major> b[2];
#pragma unroll
        for (int i = 0; i < 2; i++)
            wmma::load_matrix_sync(a[i], As + (row0 + i * 16) * LDT + k * 8, LDT);
#pragma unroll
        for (int j = 0; j < 2; j++)
            wmma::load_matrix_sync(b[j], Bs + (col0 + j * 16) * LDT + k * 8, LDT);
#pragma unroll
        for (int i = 0; i < 2; i++)
#pragma unroll
            for (int j = 0; j < 2; j++)
                wmma::mma_sync(acc[i][j], a[i], b[j], acc[i][j]);
    }
    __syncthreads();

    // stage accumulators to smem (reuse As region), then vectorized global write + bias
    float* Cs = sm;   // [TM][TN]
#pragma unroll
    for (int i = 0; i < 2; i++)
#pragma unroll
        for (int j = 0; j < 2; j++)
            wmma::store_matrix_sync(Cs + (row0 + i * 16) * TN + col0 + j * 16,
                                    acc[i][j], TN, wmma::mem_row_major);
    __syncthreads();

    for (int slot = tid; slot < TM * TN / 4; slot += 256) {
        int r = slot / (TN / 4);
        int c4 = (slot % (TN / 4)) * 4;
        float4 v = *(float4*)(Cs + r * TN + c4);
        if (bias != nullptr) {
            v.x += bias[bn + c4 + 0];
            v.y += bias[bn + c4 + 1];
            v.z += bias[bn + c4 + 2];
            v.w += bias[bn + c4 + 3];
        }
        *(float4*)(C + (size_t)(bm + r) * J + bn + c4) = v;
    }
}

// ---------------- GRU elementwise combine ----------------
__device__ __forceinline__ float sigf(float x) { return 1.0f / (1.0f + expf(-x)); }

__global__ void gru_combine_kernel(const float* __restrict__ gi, const float* __restrict__ gh,
                                   const float* __restrict__ hold, float* __restrict__ hout) {
    int idx = blockIdx.x * blockDim.x + threadIdx.x;
    if (idx >= NN * 32) return;
    int n = idx >> 5;
    int c = (idx & 31) * 4;
    const float* gir = gi + (size_t)n * 384;
    const float* ghr = gh + (size_t)n * 384;
    float4 ir = *(const float4*)(gir + c);
    float4 iz = *(const float4*)(gir + 128 + c);
    float4 in4 = *(const float4*)(gir + 256 + c);
    float4 hr = *(const float4*)(ghr + c);
    float4 hz = *(const float4*)(ghr + 128 + c);
    float4 hn = *(const float4*)(ghr + 256 + c);
    float4 h = *(const float4*)(hold + (size_t)n * 128 + c);
    float4 o;
    { float r = sigf(ir.x + hr.x), z = sigf(iz.x + hz.x);
      float nn = tanhf(in4.x + r * hn.x); o.x = (1.f - z) * nn + z * h.x; }
    { float r = sigf(ir.y + hr.y), z = sigf(iz.y + hz.y);
      float nn = tanhf(in4.y + r * hn.y); o.y = (1.f - z) * nn + z * h.y; }
    { float r = sigf(ir.z + hr.z), z = sigf(iz.z + hz.z);
      float nn = tanhf(in4.z + r * hn.z); o.z = (1.f - z) * nn + z * h.z; }
    { float r = sigf(ir.w + hr.w), z = sigf(iz.w + hz.w);
      float nn = tanhf(in4.w + r * hn.w); o.w = (1.f - z) * nn + z * h.w; }
    *(float4*)(hout + (size_t)n * 128 + c) = o;
}

// ---------------- pooling / MLP ----------------
__global__ void cnt_kernel(const int* __restrict__ batch, float* __restrict__ cnt, int n) {
    int i = blockIdx.x * blockDim.x + threadIdx.x;
    if (i < n) atomicAdd(&cnt[batch[i]], 1.0f);
}
__global__ void pool_kernel(const float* __restrict__ x, const int* __restrict__ batch,
                            float* __restrict__ pool) {
    int idx = blockIdx.x * blockDim.x + threadIdx.x;
    if (idx >= NN * 32) return;
    int n = idx >> 5;
    int c = (idx & 31) * 4;
    int g = batch[n];
    float4 v = *(const float4*)(x + (size_t)n * 128 + c);
    float* o = pool + (size_t)g * 128 + c;
    asm volatile("red.global.add.v4.f32 [%0], {%1,%2,%3,%4};"
                 :: "l"(o), "f"(v.x), "f"(v.y), "f"(v.z), "f"(v.w) : "memory");
}
__global__ void mlp_kernel(const float* __restrict__ pool, const float* __restrict__ cnt,
                           const float* __restrict__ pt,
                           const float* __restrict__ fc1w, const float* __restrict__ fc1b,
                           const float* __restrict__ fc2w, const float* __restrict__ fc2b,
                           const float* __restrict__ fclw, const float* __restrict__ fclb,
                           float* __restrict__ out) {
    __shared__ float h1[GG * 80];
    __shared__ float h2[GG * 80];
    int tid = threadIdx.x;
    for (int t = tid; t < GG * 80; t += blockDim.x) {
        int g = t / 80, j = t - (t / 80) * 80;
        float ic = 1.0f / fmaxf(cnt[g], 1.0f);
        float acc = fc1b[j];
        const float* w = fc1w + j * 129;
        const float* p = pool + g * 128;
        for (int k = 0; k < 128; k++) acc = fmaf(p[k] * ic, w[k], acc);
        acc = fmaf(pt[g], w[128], acc);
        h1[t] = acc > 0.f ? acc : 0.01f * acc;
    }
    __syncthreads();
    for (int t = tid; t < GG * 80; t += blockDim.x) {
        int g = t / 80, j = t - (t / 80) * 80;
        float acc = fc2b[j];
        const float* w = fc2w + j * 80;
        const float* hh = h1 + g * 80;
        for (int k = 0; k < 80; k++) acc = fmaf(hh[k], w[k], acc);
        h2[t] = acc > 0.f ? acc : 0.01f * acc;
    }
    __syncthreads();
    for (int t = tid; t < GG * OUTD; t += blockDim.x) {
        int g = t / OUTD, o = t - (t / OUTD) * OUTD;
        float acc = fclb[o];
        const float* w = fclw + o * 80;
        const float* hh = h2 + g * 80;
        for (int k = 0; k < 80; k++) acc = fmaf(hh[k], w[k], acc);
        out[t] = acc;
    }
}

// ---------------- host launcher ----------------
extern "C" void kernel_launch(void* const* d_in, const int* in_sizes, int n_in,
                              void* d_out, int out_size) {
    (void)in_sizes; (void)n_in; (void)out_size;
    const float* x     = (const float*)d_in[0];
    const int*   eidx  = (const int*)d_in[1];
    const int*   eattr = (const int*)d_in[2];
    const int*   batch = (const int*)d_in[3];
    const float* pt    = (const float*)d_in[4];
    const float* W     = (const float*)d_in[5];
    const float* wih   = (const float*)d_in[6];
    const float* whh   = (const float*)d_in[7];
    const float* bih   = (const float*)d_in[8];
    const float* bhh   = (const float*)d_in[9];
    const float* fc1w  = (const float*)d_in[10];
    const float* fc1b  = (const float*)d_in[11];
    const float* fc2w  = (const float*)d_in[12];
    const float* fc2b  = (const float*)d_in[13];
    const float* fclw  = (const float*)d_in[14];
    const float* fclb  = (const float*)d_in[15];
    float* out = (float*)d_out;

    const int* src = eidx;
    const int* dst = eidx + EE;

    float *xp, *hp, *aggp, *accp, *gip, *ghp, *degp, *wcp, *poolp, *cntp;
    int *bsrcp, *bdstp, *bmetap;
    cudaGetSymbolAddress((void**)&xp,    g_x);
    cudaGetSymbolAddress((void**)&hp,    g_h);
    cudaGetSymbolAddress((void**)&aggp,  g_agg);
    cudaGetSymbolAddress((void**)&accp,  g_acc);
    cudaGetSymbolAddress((void**)&gip,   g_gi);
    cudaGetSymbolAddress((void**)&ghp,   g_gh);
    cudaGetSymbolAddress((void**)&degp,  g_deg);
    cudaGetSymbolAddress((void**)&wcp,   g_wc);
    cudaGetSymbolAddress((void**)&poolp, g_pool);
    cudaGetSymbolAddress((void**)&cntp,  g_cnt);
    cudaGetSymbolAddress((void**)&bsrcp, g_bsrc);
    cudaGetSymbolAddress((void**)&bdstp, g_bdst);
    cudaGetSymbolAddress((void**)&bmetap, g_bmeta);

    cudaFuncSetAttribute(wmma_gemm_nt, cudaFuncAttributeMaxDynamicSharedMemorySize, GEMM_SMEM);

    const int ND4 = NN * DD / 4;
    const int TB = 256;
    dim3 gemm_grid(384 / TN, NP / TM);   // (6, 782)  N-tiles fastest -> A reuse in L2
    dim3 wc_grid(128 / TN, 384 / TM);    // (2, 3)

    // --- preprocessing ---
    zero_kernel<<<(SS * NP / 4 + TB - 1) / TB, TB>>>(degp, SS * NP / 4);
    deg_count_kernel<<<(EE + TB - 1) / TB, TB>>>(dst, eattr, degp, EE);
    invdeg_kernel<<<(SS * NP + TB - 1) / TB, TB>>>(degp, SS * NP);
    zero_ints<<<1, 32>>>(bmetap, 6);
    bucket_count_kernel<<<(EE + TB - 1) / TB, TB>>>(eattr, bmetap, EE);
    bucket_scan_kernel<<<1, 1>>>(bmetap);
    bucket_fill_kernel<<<(EE + TB - 1) / TB, TB>>>(src, dst, eattr, bmetap, bsrcp, bdstp, EE);
    copy_kernel<<<(ND4 + TB - 1) / TB, TB>>>(xp, x, ND4);
    zero_kernel<<<((NP - NN) * DD / 4 + TB - 1) / TB, TB>>>(xp + (size_t)NN * DD,
                                                            (NP - NN) * DD / 4);
    zero_kernel<<<((NP - NN) * DD / 4 + TB - 1) / TB, TB>>>(hp + (size_t)NN * DD,
                                                            (NP - NN) * DD / 4);
    // combined weights Wc[s,i][j,k'] = sum_k wih[s][j,k] * W[s,i][k',k]
    for (int s = 0; s < SS; s++)
        for (int i = 0; i < 2; i++)
            wmma_gemm_nt<<<wc_grid, TB, GEMM_SMEM>>>(
                wih + (size_t)s * 384 * 128, W + (size_t)(s * 2 + i) * 128 * 128,
                wcp + (size_t)(s * 2 + i) * 384 * 128, nullptr, nullptr, 128);

    // --- main GGNN loop ---
    for (int pass = 0; pass < 2; pass++) {
        zero_kernel<<<(ND4 + TB - 1) / TB, TB>>>(accp, ND4);
        for (int s = 0; s < SS; s++) {
            for (int i = 0; i < 2; i++) {
                const float* hin = (i == 0) ? xp : hp;
                // agg = scatter-sum of hin over type-s edges (scatter commutes with @W)
                zero_kernel<<<(NP * DD / 4 + TB - 1) / TB, TB>>>(aggp, NP * DD / 4);
                edge_scatter_bucket<<<1480, TB>>>(bsrcp, bdstp, bmetap, s, hin, aggp);
                // gh = hin @ whh[s]^T + bhh[s]
                wmma_gemm_nt<<<gemm_grid, TB, GEMM_SMEM>>>(
                    hin, whh + (size_t)s * 384 * 128, ghp, bhh + s * 384, nullptr, 384);
                // gi = (invdeg .* agg) @ Wc[s,i]^T + bih[s]
                wmma_gemm_nt<<<gemm_grid, TB, GEMM_SMEM>>>(
                    aggp, wcp + (size_t)(s * 2 + i) * 384 * 128, gip, bih + s * 384,
                    degp + s * NP, 384);
                gru_combine_kernel<<<(NN * 32 + TB - 1) / TB, TB>>>(gip, ghp, hin, hp);
            }
            add_kernel<<<(ND4 + TB - 1) / TB, TB>>>(accp, hp, ND4);
        }
        scale_copy_kernel<<<(ND4 + TB - 1) / TB, TB>>>(xp, accp, 1.0f / 3.0f, ND4);
    }

    // --- pooling + MLP ---
    zero_kernel<<<(GG * DD / 4 + TB - 1) / TB, TB>>>(poolp, GG * DD / 4);
    zero_kernel<<<1, GG / 4>>>(cntp, GG / 4);
    cnt_kernel<<<(NN + TB - 1) / TB, TB>>>(batch, cntp, NN);
    pool_kernel<<<(NN * 32 + TB - 1) / TB, TB>>>(xp, batch, poolp);
    mlp_kernel<<<1, 256>>>(poolp, cntp, pt, fc1w, fc1b, fc2w, fc2b, fclw, fclb, out);
}